// round 8
// baseline (speedup 1.0000x reference)
#include <cuda_runtime.h>
#include <cstdint>

// Problem constants
#define B_DIM 64
#define T_DIM 32
#define J_DIM 128
#define N_DIM 64
#define IN_F  4096
#define OUT_F 256
#define NTILES2 (B_DIM * T_DIM * 2)   // 4096 (bt x n-half)

// Transposed, tf32-rounded weight: WT[in_f][out_f]
__device__ float g_WT[IN_F * OUT_F];

__device__ __forceinline__ uint32_t f32_to_tf32(float x) {
    uint32_t r;
    asm("cvt.rna.tf32.f32 %0, %1;" : "=r"(r) : "f"(x));
    return r;
}

__device__ __forceinline__ void cp_async16(void* smem_dst, const void* gsrc) {
    uint32_t d = (uint32_t)__cvta_generic_to_shared(smem_dst);
    asm volatile("cp.async.cg.shared.global [%0], [%1], 16;\n" :: "r"(d), "l"(gsrc));
}
#define CP_COMMIT() asm volatile("cp.async.commit_group;\n" ::: "memory")
#define CP_WAIT0()  asm volatile("cp.async.wait_group 0;\n" ::: "memory")

// ---------------------------------------------------------------------------
// Kernel 1: transpose full_weight (OUT_F, IN_F) -> g_WT (IN_F, OUT_F), tf32-RNA.
// ---------------------------------------------------------------------------
__global__ void transpose_cvt_kernel(const float* __restrict__ Wfull) {
    __shared__ float tile[32][33];
    int tx = threadIdx.x, ty = threadIdx.y;
    int bx = blockIdx.x;  // IN_F / 32
    int by = blockIdx.y;  // OUT_F / 32
    #pragma unroll
    for (int i = 0; i < 32; i += 8)
        tile[ty + i][tx] = Wfull[(size_t)(by * 32 + ty + i) * IN_F + bx * 32 + tx];
    __syncthreads();
    #pragma unroll
    for (int i = 0; i < 32; i += 8) {
        uint32_t v = f32_to_tf32(tile[tx][ty + i]);
        ((uint32_t*)g_WT)[(size_t)(bx * 32 + ty + i) * OUT_F + by * 32 + tx] = v;
    }
}

// ---------------------------------------------------------------------------
// Kernel 2: persistent CTAs, 2 CTAs/SM, 256 thr (8 warps).
// Tile = (bt, nh): Y[128 x 128] = X[128 x 64] @ Wg[64 x 128(nh slice)].
// Xs double-buffered, Ws single-buffered (gather latency hidden by stores +
// the co-resident anti-phased CTA).
// ---------------------------------------------------------------------------
#define XS_LD 68    // Xs [128][68]: A-frag banks 4*qrow+qcol -> conflict-free
#define WS_LD 136   // Ws [64][136]: B-frag banks 8*qcol+qrow -> conflict-free
#define XS_ELEMS (128 * XS_LD)
#define WS_ELEMS (64 * WS_LD)

__device__ __forceinline__ void prefetch_X(int bt, float* Xs,
                                           const float* __restrict__ X, int tid) {
    const float4* Xg = (const float4*)(X + (size_t)bt * (J_DIM * N_DIM));
    #pragma unroll
    for (int i = 0; i < 8; i++) {
        int e = tid + i * 256;           // 0..2047 16B chunks
        int j = e >> 4;
        int c = e & 15;
        cp_async16(Xs + j * XS_LD + c * 4, Xg + e);
    }
    CP_COMMIT();
}

__device__ __forceinline__ void gather_W(int bt, int nh, float* Ws,
                                         const int* __restrict__ IDX,
                                         int lane, int wid) {
    const int b = bt >> 5;
    const int t = bt & 31;
    int idx_val = 0;
    if (lane < 8)
        idx_val = IDX[((size_t)b * 64 + wid * 8 + lane) * 32 + t];
    int rl  = lane >> 2;                               // 0..7 row within warp
    int row = wid * 8 + rl;                            // 0..63
    int idx_r = __shfl_sync(0xffffffffu, idx_val, rl);
    const float4* src = (const float4*)(g_WT + (size_t)idx_r * OUT_F + nh * 128);
    float4* dst = (float4*)(Ws + row * WS_LD);
    int c0 = lane & 3;                                 // 4 lanes per row
    #pragma unroll
    for (int i = 0; i < 8; i++)                        // 8 x 16B = 128B... x4 lanes = 512B/row
        cp_async16(dst + c0 + i * 4, src + c0 + i * 4);
    CP_COMMIT();
}

__global__ void __launch_bounds__(256, 2)
masklinear_kernel(const float* __restrict__ X,
                  const int* __restrict__ IDX,
                  float* __restrict__ Y) {
    extern __shared__ float smem[];
    float* Ws = smem + 2 * XS_ELEMS;      // single stage
    const int tid  = threadIdx.x;
    const int lane = tid & 31;
    const int wid  = tid >> 5;            // 0..7

    // Warp layout: 4(m) x 2(n); warp tile 32 x 64
    const int m0   = (wid >> 1) * 32;
    const int n0   = (wid & 1) * 64;
    const int qrow = lane >> 2;           // 0..7
    const int qcol = lane & 3;            // 0..3

    // Prologue: prefetch first tile
    int tile = blockIdx.x;
    {
        prefetch_X(tile >> 1, smem, X, tid);
        gather_W(tile >> 1, tile & 1, Ws, IDX, lane, wid);
    }

    int s = 0;
    for (; tile < NTILES2; tile += gridDim.x) {
        const int bt = tile >> 1;
        const int nh = tile & 1;

        CP_WAIT0();
        __syncthreads();                  // X(tile) in Xs[s], W(tile) in Ws

        float* Xs = smem + s * XS_ELEMS;
        const int ntile = tile + gridDim.x;

        // Prefetch next X into the other stage (overlaps compute)
        if (ntile < NTILES2)
            prefetch_X(ntile >> 1, smem + (s ^ 1) * XS_ELEMS, X, tid);

        // ---- Compute: warp tile 32 x 64, K = 64 in 8 steps of k8 ----
        float c[2][8][4];
        #pragma unroll
        for (int mt = 0; mt < 2; mt++)
            #pragma unroll
            for (int nt = 0; nt < 8; nt++)
                #pragma unroll
                for (int i = 0; i < 4; i++) c[mt][nt][i] = 0.f;

        #pragma unroll
        for (int kt = 0; kt < 8; kt++) {
            const int k0 = kt * 8;
            uint32_t a[2][4];
            #pragma unroll
            for (int mt = 0; mt < 2; mt++) {
                const float* Ab = Xs + (m0 + mt * 16 + qrow) * XS_LD + k0 + qcol;
                a[mt][0] = f32_to_tf32(Ab[0]);
                a[mt][1] = f32_to_tf32(Ab[8 * XS_LD]);
                a[mt][2] = f32_to_tf32(Ab[4]);
                a[mt][3] = f32_to_tf32(Ab[8 * XS_LD + 4]);
            }
            uint32_t bf[8][2];
            #pragma unroll
            for (int nt = 0; nt < 8; nt++) {
                const uint32_t* Bb =
                    (const uint32_t*)(Ws + (k0 + qcol) * WS_LD + n0 + nt * 8 + qrow);
                bf[nt][0] = Bb[0];
                bf[nt][1] = Bb[4 * WS_LD];
            }
            #pragma unroll
            for (int mt = 0; mt < 2; mt++)
                #pragma unroll
                for (int nt = 0; nt < 8; nt++) {
                    asm volatile(
                        "mma.sync.aligned.m16n8k8.row.col.f32.tf32.tf32.f32 "
                        "{%0,%1,%2,%3}, {%4,%5,%6,%7}, {%8,%9}, {%0,%1,%2,%3};\n"
                        : "+f"(c[mt][nt][0]), "+f"(c[mt][nt][1]),
                          "+f"(c[mt][nt][2]), "+f"(c[mt][nt][3])
                        : "r"(a[mt][0]), "r"(a[mt][1]), "r"(a[mt][2]), "r"(a[mt][3]),
                          "r"(bf[nt][0]), "r"(bf[nt][1]));
                }
        }

        __syncthreads();                  // all warps done reading Ws

        // Gather next tile's W slice (latency hidden by stores + sibling CTA)
        if (ntile < NTILES2)
            gather_W(ntile >> 1, ntile & 1, Ws, IDX, lane, wid);

        // ---- Store Y tile (full 32B sectors via float2) ----
        float* Yb = Y + (size_t)bt * (J_DIM * OUT_F) + nh * 128;
        #pragma unroll
        for (int mt = 0; mt < 2; mt++) {
            #pragma unroll
            for (int nt = 0; nt < 8; nt++) {
                int row = m0 + mt * 16 + qrow;
                int col = n0 + nt * 8 + qcol * 2;
                *(float2*)(Yb + (size_t)row * OUT_F + col) =
                    make_float2(c[mt][nt][0], c[mt][nt][1]);
                *(float2*)(Yb + (size_t)(row + 8) * OUT_F + col) =
                    make_float2(c[mt][nt][2], c[mt][nt][3]);
            }
        }

        s ^= 1;
    }
}

// ---------------------------------------------------------------------------
extern "C" void kernel_launch(void* const* d_in, const int* in_sizes, int n_in,
                              void* d_out, int out_size) {
    const float* X     = (const float*)d_in[0];   // (B,T,J,N) f32
    const int*   IDX   = (const int*)d_in[1];     // (B,N,T) int32
    const float* Wfull = (const float*)d_in[2];   // (OUT_F, IN_F) f32
    float*       Y     = (float*)d_out;           // (B,T,J,OUT_F) f32

    int nsm = 148;
    cudaDeviceGetAttribute(&nsm, cudaDevAttrMultiProcessorCount, 0);
    if (nsm <= 0) nsm = 148;
    int grid = 2 * nsm;
    if (grid > NTILES2) grid = NTILES2;

    const size_t smem_bytes = (2 * XS_ELEMS + WS_ELEMS) * sizeof(float); // 104448
    cudaFuncSetAttribute(masklinear_kernel,
                         cudaFuncAttributeMaxDynamicSharedMemorySize,
                         (int)smem_bytes);

    transpose_cvt_kernel<<<dim3(IN_F / 32, OUT_F / 32), dim3(32, 8)>>>(Wfull);
    masklinear_kernel<<<grid, 256, smem_bytes>>>(X, IDX, Y);
}

// round 9
// speedup vs baseline: 1.0853x; 1.0853x over previous
#include <cuda_runtime.h>
#include <cstdint>

// Problem constants
#define B_DIM 64
#define T_DIM 32
#define J_DIM 128
#define N_DIM 64
#define IN_F  4096
#define OUT_F 256
#define NTILES (B_DIM * T_DIM)   // 2048
#define MAXQ 16                  // max tiles per CTA (grid >= 128)

// Transposed, tf32-rounded weight: WT[in_f][out_f]
__device__ float g_WT[IN_F * OUT_F];

__device__ __forceinline__ uint32_t f32_to_tf32(float x) {
    uint32_t r;
    asm("cvt.rna.tf32.f32 %0, %1;" : "=r"(r) : "f"(x));
    return r;
}

__device__ __forceinline__ void cp_async16(void* smem_dst, const void* gsrc) {
    uint32_t d = (uint32_t)__cvta_generic_to_shared(smem_dst);
    asm volatile("cp.async.cg.shared.global [%0], [%1], 16;\n" :: "r"(d), "l"(gsrc));
}
// cp.async with evict_last L2 policy (keeps g_WT resident against Y streams)
__device__ __forceinline__ void cp_async16_el(void* smem_dst, const void* gsrc,
                                              uint64_t pol) {
    uint32_t d = (uint32_t)__cvta_generic_to_shared(smem_dst);
    asm volatile("cp.async.cg.shared.global.L2::cache_hint [%0], [%1], 16, %2;\n"
                 :: "r"(d), "l"(gsrc), "l"(pol));
}
#define CP_COMMIT() asm volatile("cp.async.commit_group;\n" ::: "memory")
#define CP_WAIT0()  asm volatile("cp.async.wait_group 0;\n" ::: "memory")

// ---------------------------------------------------------------------------
// Kernel 1: transpose full_weight (OUT_F, IN_F) -> g_WT (IN_F, OUT_F), tf32-RNA.
// ---------------------------------------------------------------------------
__global__ void transpose_cvt_kernel(const float* __restrict__ Wfull) {
    __shared__ float tile[32][33];
    int tx = threadIdx.x, ty = threadIdx.y;
    int bx = blockIdx.x;  // IN_F / 32
    int by = blockIdx.y;  // OUT_F / 32
    #pragma unroll
    for (int i = 0; i < 32; i += 8)
        tile[ty + i][tx] = Wfull[(size_t)(by * 32 + ty + i) * IN_F + bx * 32 + tx];
    __syncthreads();
    #pragma unroll
    for (int i = 0; i < 32; i += 8) {
        uint32_t v = f32_to_tf32(tile[tx][ty + i]);
        ((uint32_t*)g_WT)[(size_t)(bx * 32 + ty + i) * OUT_F + by * 32 + tx] = v;
    }
}

// ---------------------------------------------------------------------------
// Kernel 2: persistent CTAs (512 thr, 16 warps), double-buffered cp.async.
// Per tile: Y[128 x 256] = X[128 x 64] @ Wg[64 x 256].
// Warp grid 4(m) x 4(n), warp tile 32 x 64 (best measured geometry, R5).
// ---------------------------------------------------------------------------
#define XS_LD 68    // Xs [128][68]: A-frag banks 4*qrow+qcol -> conflict-free
#define WS_LD 264   // Ws [64][264]: B-frag banks 8*qcol+qrow -> conflict-free
#define XS_ELEMS (128 * XS_LD)
#define WS_ELEMS (64 * WS_LD)
#define STAGE_ELEMS (XS_ELEMS + WS_ELEMS)

__global__ void __launch_bounds__(512, 1)
masklinear_kernel(const float* __restrict__ X,
                  const int* __restrict__ IDX,
                  float* __restrict__ Y) {
    extern __shared__ float smem[];
    __shared__ int s_idx[MAXQ * 64];

    const int tid  = threadIdx.x;
    const int lane = tid & 31;
    const int wid  = tid >> 5;            // 0..15

    // Warp layout: 4(m) x 4(n); warp tile 32 x 64
    const int wm   = wid >> 2;
    const int wn   = wid & 3;
    const int m0   = wm * 32;
    const int n0   = wn * 64;
    const int qrow = lane >> 2;           // 0..7
    const int qcol = lane & 3;            // 0..3

    // evict_last policy for weight-table gathers
    uint64_t pol;
    asm volatile("createpolicy.fractional.L2::evict_last.b64 %0, 1.0;" : "=l"(pol));

    // ---- Preload ALL my tiles' gather indices into smem (once) ----
    int nmine = 0;
    for (int bt = blockIdx.x; bt < NTILES; bt += gridDim.x) nmine++;
    for (int e = tid; e < nmine * 64; e += 512) {
        int q = e >> 6, n = e & 63;
        int bt = blockIdx.x + q * gridDim.x;
        int b = bt >> 5, t = bt & 31;
        s_idx[e] = IDX[((size_t)b * 64 + n) * 32 + t];
    }
    __syncthreads();

    // ---- prefetch (W gather first: only L2-latency-exposed read) ----
    auto prefetch_tile = [&](int bt, int q, float* Xs, float* Ws) {
        // W gather: 4 rows per warp, 8 lanes per row, 8 x 16B chunks per lane
        int rl  = lane >> 3;                           // 0..3 row within warp
        int row = wid * 4 + rl;                        // 0..63
        int idx_r = s_idx[q * 64 + row];
        const float4* src = (const float4*)(g_WT + (size_t)idx_r * OUT_F);
        float4* dst = (float4*)(Ws + row * WS_LD);
        int c0 = lane & 7;
        #pragma unroll
        for (int i = 0; i < 8; i++)
            cp_async16_el(dst + c0 + i * 8, src + c0 + i * 8, pol);

        // X tile: 128x64 f32 contiguous = 2048 x 16B chunks, 4 per thread
        const float4* Xg = (const float4*)(X + (size_t)bt * (J_DIM * N_DIM));
        #pragma unroll
        for (int i = 0; i < 4; i++) {
            int e = tid + i * 512;
            int j = e >> 4;
            int c = e & 15;
            cp_async16(Xs + j * XS_LD + c * 4, Xg + e);
        }
        CP_COMMIT();
    };

    // Prologue: prefetch first tile into stage 0
    int bt = blockIdx.x;
    prefetch_tile(bt, 0, smem, smem + XS_ELEMS);

    int s = 0, q = 0;
    for (; bt < NTILES; bt += gridDim.x, q++) {
        CP_WAIT0();
        __syncthreads();

        float* Xs = smem + s * STAGE_ELEMS;
        float* Ws = Xs + XS_ELEMS;

        // Prefetch next tile into the other stage (overlaps compute)
        int nbt = bt + gridDim.x;
        if (nbt < NTILES) {
            float* nXs = smem + (s ^ 1) * STAGE_ELEMS;
            prefetch_tile(nbt, q + 1, nXs, nXs + XS_ELEMS);
        }

        // ---- Compute: warp tile 32 x 64, K = 64 in 8 steps of k8 ----
        float c[2][8][4];
        #pragma unroll
        for (int mt = 0; mt < 2; mt++)
            #pragma unroll
            for (int nt = 0; nt < 8; nt++)
                #pragma unroll
                for (int i = 0; i < 4; i++) c[mt][nt][i] = 0.f;

        #pragma unroll
        for (int kt = 0; kt < 8; kt++) {
            const int k0 = kt * 8;
            uint32_t a[2][4];
            #pragma unroll
            for (int mt = 0; mt < 2; mt++) {
                const float* Ab = Xs + (m0 + mt * 16 + qrow) * XS_LD + k0 + qcol;
                a[mt][0] = f32_to_tf32(Ab[0]);
                a[mt][1] = f32_to_tf32(Ab[8 * XS_LD]);
                a[mt][2] = f32_to_tf32(Ab[4]);
                a[mt][3] = f32_to_tf32(Ab[8 * XS_LD + 4]);
            }
            uint32_t bf[8][2];
            #pragma unroll
            for (int nt = 0; nt < 8; nt++) {
                const uint32_t* Bb =
                    (const uint32_t*)(Ws + (k0 + qcol) * WS_LD + n0 + nt * 8 + qrow);
                bf[nt][0] = Bb[0];
                bf[nt][1] = Bb[4 * WS_LD];
            }
            #pragma unroll
            for (int mt = 0; mt < 2; mt++)
                #pragma unroll
                for (int nt = 0; nt < 8; nt++) {
                    asm volatile(
                        "mma.sync.aligned.m16n8k8.row.col.f32.tf32.tf32.f32 "
                        "{%0,%1,%2,%3}, {%4,%5,%6,%7}, {%8,%9}, {%0,%1,%2,%3};\n"
                        : "+f"(c[mt][nt][0]), "+f"(c[mt][nt][1]),
                          "+f"(c[mt][nt][2]), "+f"(c[mt][nt][3])
                        : "r"(a[mt][0]), "r"(a[mt][1]), "r"(a[mt][2]), "r"(a[mt][3]),
                          "r"(bf[nt][0]), "r"(bf[nt][1]));
                }
        }

        // ---- Store Y tile: streaming (evict-first) full-sector float2 ----
        float* Yb = Y + (size_t)bt * (J_DIM * OUT_F);
        #pragma unroll
        for (int mt = 0; mt < 2; mt++) {
            #pragma unroll
            for (int nt = 0; nt < 8; nt++) {
                int row = m0 + mt * 16 + qrow;
                int col = n0 + nt * 8 + qcol * 2;
                __stcs((float2*)(Yb + (size_t)row * OUT_F + col),
                       make_float2(c[mt][nt][0], c[mt][nt][1]));
                __stcs((float2*)(Yb + (size_t)(row + 8) * OUT_F + col),
                       make_float2(c[mt][nt][2], c[mt][nt][3]));
            }
        }

        s ^= 1;
    }
}

// ---------------------------------------------------------------------------
extern "C" void kernel_launch(void* const* d_in, const int* in_sizes, int n_in,
                              void* d_out, int out_size) {
    const float* X     = (const float*)d_in[0];   // (B,T,J,N) f32
    const int*   IDX   = (const int*)d_in[1];     // (B,N,T) int32
    const float* Wfull = (const float*)d_in[2];   // (OUT_F, IN_F) f32
    float*       Y     = (float*)d_out;           // (B,T,J,OUT_F) f32

    int nsm = 148;
    cudaDeviceGetAttribute(&nsm, cudaDevAttrMultiProcessorCount, 0);
    if (nsm < 128 || nsm > NTILES) nsm = 148;   // MAXQ guard (>=128)

    const size_t smem_bytes = 2 * STAGE_ELEMS * sizeof(float);  // 204800
    cudaFuncSetAttribute(masklinear_kernel,
                         cudaFuncAttributeMaxDynamicSharedMemorySize,
                         (int)smem_bytes);

    transpose_cvt_kernel<<<dim3(IN_F / 32, OUT_F / 32), dim3(32, 8)>>>(Wfull);
    masklinear_kernel<<<nsm, 512, smem_bytes>>>(X, IDX, Y);
}